// round 3
// baseline (speedup 1.0000x reference)
#include <cuda_runtime.h>

#define TB    8          // samples per block
#define NJ    17
#define DIN   3
#define HH    64
#define DOUT  256
#define ROWS  (TB*NJ)    // 136
#define FLAT  (NJ*HH)    // 1088
#define WPAD  65
#define NTHREADS 256

// shared memory layout (floats)
#define OFF_H0   0
#define OFF_H1   (OFF_H0 + ROWS*HH)
#define OFF_WB   (OFF_H1 + ROWS*HH)
#define OFF_A    (OFF_WB + 64*WPAD)
#define OFF_W1   (OFF_A + 289)
#define OFF_B1   (OFF_W1 + 192)
#define OFF_B2   (OFF_B1 + 64)
#define OFF_B3   (OFF_B2 + 64)
#define OFF_BP1  (OFF_B3 + 64)
#define OFF_BP2  (OFF_BP1 + 64)
#define OFF_Z    (OFF_BP2 + 256)             // 512 floats (x staging / z)
#define SMEM_FLOATS (OFF_Z + TB*HH)
#define SMEM_BYTES  (SMEM_FLOATS * 4)

// g[b][i][f] = sum_j A[i][j] * h[b][j][f]   (dst/src are ROWS x 64, row-major)
__device__ __forceinline__ void aggregate(const float* __restrict__ src,
                                          float* __restrict__ dst,
                                          const float* __restrict__ sA, int tid) {
    for (int t = tid; t < ROWS * 16; t += NTHREADS) {
        int row = t >> 4, fq = t & 15;
        int b = row / NJ, i = row - b * NJ;
        const float* Ai = sA + i * NJ;
        const float* hb = src + b * FLAT + fq * 4;
        float ax = 0.f, ay = 0.f, az = 0.f, aw = 0.f;
        #pragma unroll
        for (int j = 0; j < NJ; j++) {
            float a = Ai[j];
            float4 hv = *(const float4*)(hb + j * HH);
            ax = fmaf(a, hv.x, ax);
            ay = fmaf(a, hv.y, ay);
            az = fmaf(a, hv.z, az);
            aw = fmaf(a, hv.w, aw);
        }
        float4 r; r.x = ax; r.y = ay; r.z = az; r.w = aw;
        *(float4*)(dst + row * HH + fq * 4) = r;
    }
}

// Hout[r][o] = act(bias[o] + sum_f G[r][f] * W[o][f])
// W in smem [64][WPAD]; each thread caches its W row in registers.
__device__ __forceinline__ void linear64(const float* __restrict__ G,
                                         float* __restrict__ Hout,
                                         const float* __restrict__ sW,
                                         const float* __restrict__ sBias,
                                         bool do_relu, int tid) {
    int lane = tid & 31;
    int warp = tid >> 5;
    int o  = ((warp & 1) << 5) + lane;   // 0..63
    int rq = warp >> 1;                  // 0..3
    float wreg[64];
    const float* wrow = sW + o * WPAD;
    #pragma unroll
    for (int f = 0; f < 64; f++) wreg[f] = wrow[f];
    float bias = sBias[o];
    for (int r = rq; r < ROWS; r += 4) {
        const float* grow = G + r * HH;
        float acc0 = bias, acc1 = 0.f;
        #pragma unroll
        for (int f = 0; f < 64; f += 8) {
            float4 ga = *(const float4*)(grow + f);
            float4 gb = *(const float4*)(grow + f + 4);
            acc0 = fmaf(ga.x, wreg[f + 0], acc0);
            acc0 = fmaf(ga.y, wreg[f + 1], acc0);
            acc0 = fmaf(ga.z, wreg[f + 2], acc0);
            acc0 = fmaf(ga.w, wreg[f + 3], acc0);
            acc1 = fmaf(gb.x, wreg[f + 4], acc1);
            acc1 = fmaf(gb.y, wreg[f + 5], acc1);
            acc1 = fmaf(gb.z, wreg[f + 6], acc1);
            acc1 = fmaf(gb.w, wreg[f + 7], acc1);
        }
        float acc = acc0 + acc1;
        if (do_relu) acc = fmaxf(acc, 0.f);
        Hout[r * HH + o] = acc;
    }
}

__global__ void __launch_bounds__(NTHREADS, 2)
gcn_fused_kernel(const float* __restrict__ x,  const float* __restrict__ A,
                 const float* __restrict__ W1, const float* __restrict__ b1,
                 const float* __restrict__ W2, const float* __restrict__ b2,
                 const float* __restrict__ W3, const float* __restrict__ b3,
                 const float* __restrict__ Wp1, const float* __restrict__ bp1,
                 const float* __restrict__ Wp2, const float* __restrict__ bp2,
                 float* __restrict__ out, int B) {
    extern __shared__ float sm[];
    float* sH0  = sm + OFF_H0;
    float* sH1  = sm + OFF_H1;
    float* sWB  = sm + OFF_WB;
    float* sA   = sm + OFF_A;
    float* sW1  = sm + OFF_W1;
    float* sB1  = sm + OFF_B1;
    float* sB2  = sm + OFF_B2;
    float* sB3  = sm + OFF_B3;
    float* sBP1 = sm + OFF_BP1;
    float* sBP2 = sm + OFF_BP2;
    float* sZ   = sm + OFF_Z;

    int tid = threadIdx.x;
    int b0  = blockIdx.x * TB;

    // ---- stage 0: constants + x + W2 ----
    // FIX (R2 bug): 289 > NTHREADS, must stride (sA[256..288] were never written).
    for (int t = tid; t < NJ * NJ; t += NTHREADS) sA[t] = A[t];
    if (tid < 192) sW1[tid] = W1[tid];
    if (tid < 64) {
        sB1[tid]  = b1[tid];
        sB2[tid]  = b2[tid];
        sB3[tid]  = b3[tid];
        sBP1[tid] = bp1[tid];
    }
    sBP2[tid] = bp2[tid];
    {
        // FIX (R1 bug): TB*NJ*DIN = 408 > NTHREADS, must grid-stride.
        int base = b0 * NJ * DIN;
        int total = B * NJ * DIN;
        for (int t = tid; t < TB * NJ * DIN; t += NTHREADS)
            sZ[t] = (base + t < total) ? x[base + t] : 0.f;
    }
    for (int idx = tid; idx < 64 * 64; idx += NTHREADS)
        sWB[(idx >> 6) * WPAD + (idx & 63)] = W2[idx];
    __syncthreads();

    // ---- layer 1: agg over x, then 3->64 linear + relu ----
    for (int t = tid; t < TB * NJ * DIN; t += NTHREADS) {
        int row = t / DIN, d = t - row * DIN;
        int b = row / NJ, i = row - b * NJ;
        const float* Ai = sA + i * NJ;
        const float* xb = sZ + b * NJ * DIN + d;
        float acc = 0.f;
        #pragma unroll
        for (int j = 0; j < NJ; j++) acc = fmaf(Ai[j], xb[j * DIN], acc);
        sH1[t] = acc;   // aggx staged in sH1
    }
    __syncthreads();
    for (int idx = tid; idx < ROWS * HH; idx += NTHREADS) {
        int row = idx >> 6, o = idx & 63;
        float a0 = sH1[row * 3 + 0];
        float a1 = sH1[row * 3 + 1];
        float a2 = sH1[row * 3 + 2];
        float acc = sB1[o];
        acc = fmaf(a0, sW1[o * 3 + 0], acc);
        acc = fmaf(a1, sW1[o * 3 + 1], acc);
        acc = fmaf(a2, sW1[o * 3 + 2], acc);
        sH0[idx] = fmaxf(acc, 0.f);
    }
    __syncthreads();

    // ---- layer 2 ----
    aggregate(sH0, sH1, sA, tid);
    __syncthreads();
    linear64(sH1, sH0, sWB, sB2, true, tid);
    __syncthreads();

    // ---- layer 3 (load W3 alongside aggregation) ----
    for (int idx = tid; idx < 64 * 64; idx += NTHREADS)
        sWB[(idx >> 6) * WPAD + (idx & 63)] = W3[idx];
    aggregate(sH0, sH1, sA, tid);
    __syncthreads();
    linear64(sH1, sH0, sWB, sB3, false, tid);
    __syncthreads();

    // ---- pool: z[b][o] = relu(bp1[o] + flat[b] . Wp1[o]) ----
    int o  = tid & 63;
    int bq = tid >> 6;            // 0..3
    int pb0 = bq * 2, pb1 = bq * 2 + 1;
    float accp0 = 0.f, accp1 = 0.f;
    for (int kt = 0; kt < FLAT / 64; kt++) {   // 17 tiles
        for (int idx = tid; idx < 64 * 16; idx += NTHREADS) {
            int oo = idx >> 4, kq = idx & 15;
            float4 v = *(const float4*)(Wp1 + oo * FLAT + kt * 64 + kq * 4);
            float* dst = sWB + oo * WPAD + kq * 4;
            dst[0] = v.x; dst[1] = v.y; dst[2] = v.z; dst[3] = v.w;
        }
        __syncthreads();
        const float* wrow = sWB + o * WPAD;
        const float* f0 = sH0 + pb0 * FLAT + kt * 64;
        const float* f1 = sH0 + pb1 * FLAT + kt * 64;
        #pragma unroll
        for (int k = 0; k < 64; k++) {
            float w = wrow[k];
            accp0 = fmaf(w, f0[k], accp0);
            accp1 = fmaf(w, f1[k], accp1);
        }
        __syncthreads();
    }
    sZ[pb0 * HH + o] = fmaxf(accp0 + sBP1[o], 0.f);
    sZ[pb1 * HH + o] = fmaxf(accp1 + sBP1[o], 0.f);
    __syncthreads();

    // ---- output: out[b][oo] = bp2[oo] + z[b] . Wp2[oo] ----
    for (int ot = 0; ot < 4; ot++) {
        for (int idx = tid; idx < 64 * 16; idx += NTHREADS) {
            int oo = idx >> 4, fq = idx & 15;
            float4 v = *(const float4*)(Wp2 + (ot * 64 + oo) * HH + fq * 4);
            float* dst = sWB + oo * WPAD + fq * 4;
            dst[0] = v.x; dst[1] = v.y; dst[2] = v.z; dst[3] = v.w;
        }
        __syncthreads();
        const float* wrow = sWB + o * WPAD;
        const float* z0 = sZ + pb0 * HH;
        const float* z1 = sZ + pb1 * HH;
        float acc0 = sBP2[ot * 64 + o];
        float acc1 = acc0;
        #pragma unroll
        for (int f = 0; f < 64; f++) {
            float w = wrow[f];
            acc0 = fmaf(w, z0[f], acc0);
            acc1 = fmaf(w, z1[f], acc1);
        }
        if (b0 + pb0 < B) out[(b0 + pb0) * DOUT + ot * 64 + o] = acc0;
        if (b0 + pb1 < B) out[(b0 + pb1) * DOUT + ot * 64 + o] = acc1;
        __syncthreads();
    }
}

extern "C" void kernel_launch(void* const* d_in, const int* in_sizes, int n_in,
                              void* d_out, int out_size) {
    const float* x   = (const float*)d_in[0];
    const float* A   = (const float*)d_in[1];
    const float* W1  = (const float*)d_in[2];
    const float* b1  = (const float*)d_in[3];
    const float* W2  = (const float*)d_in[4];
    const float* b2  = (const float*)d_in[5];
    const float* W3  = (const float*)d_in[6];
    const float* b3  = (const float*)d_in[7];
    const float* Wp1 = (const float*)d_in[8];
    const float* bp1 = (const float*)d_in[9];
    const float* Wp2 = (const float*)d_in[10];
    const float* bp2 = (const float*)d_in[11];
    float* out = (float*)d_out;

    int B = in_sizes[0] / (NJ * DIN);
    int grid = (B + TB - 1) / TB;

    cudaFuncSetAttribute(gcn_fused_kernel,
                         cudaFuncAttributeMaxDynamicSharedMemorySize, SMEM_BYTES);
    gcn_fused_kernel<<<grid, NTHREADS, SMEM_BYTES>>>(
        x, A, W1, b1, W2, b2, W3, b3, Wp1, bp1, Wp2, bp2, out, B);
}

// round 4
// speedup vs baseline: 1.3507x; 1.3507x over previous
#include <cuda_runtime.h>

#define TB    8          // samples per block
#define NJ    17
#define DIN   3
#define HH    64
#define DOUT  256
#define ROWS  (TB*NJ)    // 136
#define FLAT  (NJ*HH)    // 1088
#define WPAD  65
#define NTHREADS 256

typedef unsigned long long ull;

// shared memory layout (floats) — all buffers 16B-aligned
#define OFF_H0   0
#define OFF_H1   (OFF_H0 + ROWS*HH)          // 8704
#define OFF_WA   (OFF_H1 + ROWS*HH)          // 17408
#define OFF_WB   (OFF_WA + 64*WPAD)          // 21568
#define OFF_A    (OFF_WB + 64*WPAD)          // 25728
#define OFF_W1   (OFF_A + 292)               // 26020 (289 rounded to 4)
#define OFF_B1   (OFF_W1 + 192)
#define OFF_B2   (OFF_B1 + 64)
#define OFF_B3   (OFF_B2 + 64)
#define OFF_BP1  (OFF_B3 + 64)
#define OFF_BP2  (OFF_BP1 + 64)
#define OFF_Z    (OFF_BP2 + 256)             // 16B aligned
#define SMEM_FLOATS (OFF_Z + TB*HH)
#define SMEM_BYTES  (SMEM_FLOATS * 4)

// ---- packed f32x2 helpers (sm_103a FFMA2 — PTX-only) ----
__device__ __forceinline__ ull pk2(float lo, float hi) {
    ull r; asm("mov.b64 %0, {%1, %2};" : "=l"(r) : "f"(lo), "f"(hi)); return r;
}
__device__ __forceinline__ float2 upk2(ull v) {
    float2 f; asm("mov.b64 {%0, %1}, %2;" : "=f"(f.x), "=f"(f.y) : "l"(v)); return f;
}
__device__ __forceinline__ ull fma2(ull a, ull b, ull c) {
    ull d; asm("fma.rn.f32x2 %0, %1, %2, %3;" : "=l"(d) : "l"(a), "l"(b), "l"(c)); return d;
}

// stage a 64x64 tile (row stride rstride) from global into smem [64][WPAD]
__device__ __forceinline__ void stage64(const float* __restrict__ g, int rstride,
                                        float* __restrict__ s, int tid) {
    #pragma unroll
    for (int it = 0; it < 4; it++) {
        int idx = tid + it * NTHREADS;          // 0..1023
        int oo = idx >> 4, c4 = idx & 15;
        float4 v = *(const float4*)(g + oo * rstride + c4 * 4);
        float* d = s + oo * WPAD + c4 * 4;
        d[0] = v.x; d[1] = v.y; d[2] = v.z; d[3] = v.w;
    }
}

// g[b][i][f] = sum_j A[i][j] h[b][j][f], 4 output rows per task (amortize h reads)
__device__ __forceinline__ void aggregate2(const float* __restrict__ src,
                                           float* __restrict__ dst,
                                           const float* __restrict__ sA, int tid) {
    for (int t = tid; t < TB * 5 * 16; t += NTHREADS) {   // 640 tasks
        int fq = t & 15;
        int g  = t >> 4;           // 0..39
        int b  = g / 5, ic = g - b * 5;
        int i0 = ic * 4;
        const float* hb = src + b * FLAT + fq * 4;
        ull a0x=0,a0y=0,a1x=0,a1y=0,a2x=0,a2y=0,a3x=0,a3y=0;
        int r1 = (i0 + 1 < NJ) ? i0 + 1 : NJ - 1;
        int r2 = (i0 + 2 < NJ) ? i0 + 2 : NJ - 1;
        int r3 = (i0 + 3 < NJ) ? i0 + 3 : NJ - 1;
        #pragma unroll
        for (int j = 0; j < NJ; j++) {
            ulonglong2 hv = *(const ulonglong2*)(hb + j * HH);
            ull p0 = pk2(sA[i0 * NJ + j], sA[i0 * NJ + j]);
            ull p1 = pk2(sA[r1 * NJ + j], sA[r1 * NJ + j]);
            ull p2 = pk2(sA[r2 * NJ + j], sA[r2 * NJ + j]);
            ull p3 = pk2(sA[r3 * NJ + j], sA[r3 * NJ + j]);
            a0x = fma2(hv.x, p0, a0x); a0y = fma2(hv.y, p0, a0y);
            a1x = fma2(hv.x, p1, a1x); a1y = fma2(hv.y, p1, a1y);
            a2x = fma2(hv.x, p2, a2x); a2y = fma2(hv.y, p2, a2y);
            a3x = fma2(hv.x, p3, a3x); a3y = fma2(hv.y, p3, a3y);
        }
        float* drow = dst + (b * NJ + i0) * HH + fq * 4;
        ulonglong2 s;
        s.x = a0x; s.y = a0y; *(ulonglong2*)(drow) = s;
        if (i0 + 1 < NJ) { s.x = a1x; s.y = a1y; *(ulonglong2*)(drow + HH)     = s; }
        if (i0 + 2 < NJ) { s.x = a2x; s.y = a2y; *(ulonglong2*)(drow + 2*HH)   = s; }
        if (i0 + 3 < NJ) { s.x = a3x; s.y = a3y; *(ulonglong2*)(drow + 3*HH)   = s; }
    }
}

// Hout[r][o] = act(bias[o] + G[r] . W[o]); W rows cached packed in registers
__device__ __forceinline__ void linear64p(const float* __restrict__ G,
                                          float* __restrict__ Hout,
                                          const float* __restrict__ sW,
                                          const float* __restrict__ sBias,
                                          bool do_relu, int tid) {
    int lane = tid & 31, warp = tid >> 5;
    int o  = ((warp & 1) << 5) + lane;   // 0..63
    int rq = warp >> 1;                  // 0..3
    ull wreg[32];
    const float* wrow = sW + o * WPAD;
    #pragma unroll
    for (int i = 0; i < 32; i++) wreg[i] = pk2(wrow[2*i], wrow[2*i+1]);
    float bias = sBias[o];
    for (int r = rq; r < ROWS; r += 4) {
        const ulonglong2* grow = (const ulonglong2*)(G + r * HH);
        ull a0 = pk2(bias, 0.f), a1 = 0, a2 = 0, a3 = 0;
        #pragma unroll
        for (int q = 0; q < 16; q += 2) {
            ulonglong2 g0 = grow[q];
            ulonglong2 g1 = grow[q + 1];
            a0 = fma2(g0.x, wreg[2*q + 0], a0);
            a1 = fma2(g0.y, wreg[2*q + 1], a1);
            a2 = fma2(g1.x, wreg[2*q + 2], a2);
            a3 = fma2(g1.y, wreg[2*q + 3], a3);
        }
        float2 f0 = upk2(a0), f1 = upk2(a1), f2 = upk2(a2), f3 = upk2(a3);
        float acc = (f0.x + f0.y) + (f1.x + f1.y) + ((f2.x + f2.y) + (f3.x + f3.y));
        if (do_relu) acc = fmaxf(acc, 0.f);
        Hout[r * HH + o] = acc;
    }
}

__global__ void __launch_bounds__(NTHREADS, 2)
gcn_fused_kernel(const float* __restrict__ x,  const float* __restrict__ A,
                 const float* __restrict__ W1, const float* __restrict__ b1,
                 const float* __restrict__ W2, const float* __restrict__ b2,
                 const float* __restrict__ W3, const float* __restrict__ b3,
                 const float* __restrict__ Wp1, const float* __restrict__ bp1,
                 const float* __restrict__ Wp2, const float* __restrict__ bp2,
                 float* __restrict__ out, int B) {
    extern __shared__ float sm[];
    float* sH0  = sm + OFF_H0;
    float* sH1  = sm + OFF_H1;
    float* sWA  = sm + OFF_WA;
    float* sWB  = sm + OFF_WB;
    float* sA   = sm + OFF_A;
    float* sW1  = sm + OFF_W1;
    float* sB1  = sm + OFF_B1;
    float* sB2  = sm + OFF_B2;
    float* sB3  = sm + OFF_B3;
    float* sBP1 = sm + OFF_BP1;
    float* sBP2 = sm + OFF_BP2;
    float* sZ   = sm + OFF_Z;

    int tid = threadIdx.x;
    int b0  = blockIdx.x * TB;

    // ---- stage 0: constants + x + W2 ----
    for (int t = tid; t < NJ * NJ; t += NTHREADS) sA[t] = A[t];
    if (tid < 192) sW1[tid] = W1[tid];
    if (tid < 64) {
        sB1[tid]  = b1[tid];
        sB2[tid]  = b2[tid];
        sB3[tid]  = b3[tid];
        sBP1[tid] = bp1[tid];
    }
    sBP2[tid] = bp2[tid];
    {
        int base = b0 * NJ * DIN;
        int total = B * NJ * DIN;
        for (int t = tid; t < TB * NJ * DIN; t += NTHREADS)
            sZ[t] = (base + t < total) ? x[base + t] : 0.f;
    }
    stage64(W2, 64, sWA, tid);
    __syncthreads();

    // ---- layer 1: agg over x (DIN=3), then 3->64 linear + relu ----
    for (int t = tid; t < TB * NJ * DIN; t += NTHREADS) {
        int row = t / DIN, d = t - row * DIN;
        int b = row / NJ, i = row - b * NJ;
        const float* Ai = sA + i * NJ;
        const float* xb = sZ + b * NJ * DIN + d;
        float acc = 0.f;
        #pragma unroll
        for (int j = 0; j < NJ; j++) acc = fmaf(Ai[j], xb[j * DIN], acc);
        sH1[t] = acc;
    }
    __syncthreads();
    for (int idx = tid; idx < ROWS * HH; idx += NTHREADS) {
        int row = idx >> 6, o = idx & 63;
        float a0 = sH1[row * 3 + 0];
        float a1 = sH1[row * 3 + 1];
        float a2 = sH1[row * 3 + 2];
        float acc = sB1[o];
        acc = fmaf(a0, sW1[o * 3 + 0], acc);
        acc = fmaf(a1, sW1[o * 3 + 1], acc);
        acc = fmaf(a2, sW1[o * 3 + 2], acc);
        sH0[idx] = fmaxf(acc, 0.f);
    }
    __syncthreads();

    // ---- layer 2: aggregate (+ stage W3 into sWB concurrently), linear ----
    aggregate2(sH0, sH1, sA, tid);
    stage64(W3, 64, sWB, tid);
    __syncthreads();
    linear64p(sH1, sH0, sWA, sB2, true, tid);
    __syncthreads();

    // ---- layer 3 ----
    aggregate2(sH0, sH1, sA, tid);
    __syncthreads();
    linear64p(sH1, sH0, sWB, sB3, false, tid);
    __syncthreads();

    // ---- pool: z[b][o] = relu(bp1[o] + flat[b] . Wp1[o]), K=1088 ----
    int o  = tid & 63;
    int kq = tid >> 6;                  // 0..3, constant within warp
    ull acc[TB] = {0,0,0,0,0,0,0,0};
    stage64(Wp1, FLAT, sWA, tid);       // tile 0
    __syncthreads();
    for (int kt = 0; kt < 17; kt++) {
        const float* cur = (kt & 1) ? sWB : sWA;
        if (kt + 1 < 17) {
            float* nxt = (kt & 1) ? sWA : sWB;
            stage64(Wp1 + (kt + 1) * 64, FLAT, nxt, tid);   // overlap with compute
        }
        const float* wrow  = cur + o * WPAD + kq * 16;
        const float* hbase = sH0 + kt * 64 + kq * 16;
        #pragma unroll
        for (int s4 = 0; s4 < 4; s4++) {
            ull wp0 = pk2(wrow[s4*4 + 0], wrow[s4*4 + 1]);
            ull wp1 = pk2(wrow[s4*4 + 2], wrow[s4*4 + 3]);
            #pragma unroll
            for (int b = 0; b < TB; b++) {
                ulonglong2 hv = *(const ulonglong2*)(hbase + b * FLAT + s4 * 4);
                acc[b] = fma2(hv.x, wp0, acc[b]);
                acc[b] = fma2(hv.y, wp1, acc[b]);
            }
        }
        __syncthreads();
    }
    {   // cross-kq reduce (last tile used sWA; sWB is free)
        #pragma unroll
        for (int b = 0; b < TB; b++) {
            float2 f = upk2(acc[b]);
            sWB[kq * 512 + b * 64 + o] = f.x + f.y;
        }
        __syncthreads();
        for (int p = tid; p < TB * 64; p += NTHREADS) {
            float v = sWB[p] + sWB[512 + p] + sWB[1024 + p] + sWB[1536 + p] + sBP1[p & 63];
            sZ[p] = fmaxf(v, 0.f);
        }
        __syncthreads();
    }

    // ---- output: out[b][O] = bp2[O] + z[b] . Wp2[O], 4 tiles of 64 outputs ----
    for (int ot = 0; ot < 4; ot++) {
        stage64(Wp2 + ot * 64 * HH, HH, sWA, tid);
        __syncthreads();
        ull oacc[TB] = {0,0,0,0,0,0,0,0};
        const float* wrow = sWA + o * WPAD + kq * 16;
        #pragma unroll
        for (int s4 = 0; s4 < 4; s4++) {
            ull wp0 = pk2(wrow[s4*4 + 0], wrow[s4*4 + 1]);
            ull wp1 = pk2(wrow[s4*4 + 2], wrow[s4*4 + 3]);
            #pragma unroll
            for (int b = 0; b < TB; b++) {
                ulonglong2 hv = *(const ulonglong2*)(sZ + b * 64 + kq * 16 + s4 * 4);
                oacc[b] = fma2(hv.x, wp0, oacc[b]);
                oacc[b] = fma2(hv.y, wp1, oacc[b]);
            }
        }
        #pragma unroll
        for (int b = 0; b < TB; b++) {
            float2 f = upk2(oacc[b]);
            sWB[kq * 512 + b * 64 + o] = f.x + f.y;
        }
        __syncthreads();
        for (int p = tid; p < 512; p += NTHREADS) {
            int b = p >> 6, oo = p & 63;
            float v = sWB[p] + sWB[512 + p] + sWB[1024 + p] + sWB[1536 + p]
                    + sBP2[ot * 64 + oo];
            if (b0 + b < B) out[(b0 + b) * DOUT + ot * 64 + oo] = v;
        }
        __syncthreads();
    }
}

extern "C" void kernel_launch(void* const* d_in, const int* in_sizes, int n_in,
                              void* d_out, int out_size) {
    const float* x   = (const float*)d_in[0];
    const float* A   = (const float*)d_in[1];
    const float* W1  = (const float*)d_in[2];
    const float* b1  = (const float*)d_in[3];
    const float* W2  = (const float*)d_in[4];
    const float* b2  = (const float*)d_in[5];
    const float* W3  = (const float*)d_in[6];
    const float* b3  = (const float*)d_in[7];
    const float* Wp1 = (const float*)d_in[8];
    const float* bp1 = (const float*)d_in[9];
    const float* Wp2 = (const float*)d_in[10];
    const float* bp2 = (const float*)d_in[11];
    float* out = (float*)d_out;

    int B = in_sizes[0] / (NJ * DIN);
    int grid = (B + TB - 1) / TB;

    cudaFuncSetAttribute(gcn_fused_kernel,
                         cudaFuncAttributeMaxDynamicSharedMemorySize, SMEM_BYTES);
    gcn_fused_kernel<<<grid, NTHREADS, SMEM_BYTES>>>(
        x, A, W1, b1, W2, b2, W3, b3, Wp1, bp1, Wp2, bp2, out, B);
}